// round 16
// baseline (speedup 1.0000x reference)
#include <cuda_runtime.h>
#include <cuda_bf16.h>
#include <cuda_fp16.h>
#include <math.h>
#include <stdint.h>

#define Bb 2
#define Tt 2048
#define Cc 1024
#define Hh 16
#define Dd 64
#define Ff 4096
#define MM (Bb*Tt)
#define BHTD (Bb*Hh*Tt*Dd)

// ---------------------------------------------------------------------------
// Scratch (device globals)
// ---------------------------------------------------------------------------
__device__ float d_x2[MM*Cc];

__device__ __half d_h  [MM*Cc];
__device__ __half d_c  [MM*Cc];     // ctx
__device__ __half d_h2 [MM*Cc];
__device__ __half d_g  [MM*Ff];

// QKV packed: [mat(q/k/v)][B,H,T,D] fp16 (Q pre-scaled by 1/sqrt(D))
__device__ __half d_qkv[3*BHTD];

// transposed weights, [N][K] K-contiguous, single fp16
__device__ __half d_wqkv[3*Cc*Cc];
__device__ __half d_wo[Cc*Cc];
__device__ __half d_w1[Ff*Cc];
__device__ __half d_w2[Cc*Ff];
__device__ float d_bqkv[3*Cc];

// ---------------------------------------------------------------------------
// Helpers
// ---------------------------------------------------------------------------
__device__ __forceinline__ uint32_t smem_u32(const void* p) {
    uint32_t a;
    asm("{ .reg .u64 t; cvta.to.shared.u64 t, %1; cvt.u32.u64 %0, t; }" : "=r"(a) : "l"(p));
    return a;
}

#define CP16(dst, src) asm volatile("cp.async.cg.shared.global [%0], [%1], 16;" :: "r"(dst), "l"(src) : "memory")
#define CP_COMMIT()    asm volatile("cp.async.commit_group;" ::: "memory")
#define CP_WAIT0()     asm volatile("cp.async.wait_group 0;" ::: "memory")
#define CP_WAIT1()     asm volatile("cp.async.wait_group 1;" ::: "memory")
#define CP_WAIT2()     asm volatile("cp.async.wait_group 2;" ::: "memory")

#define LDMX4(r0,r1,r2,r3,addr) \
    asm volatile("ldmatrix.sync.aligned.m8n8.x4.shared.b16 {%0,%1,%2,%3}, [%4];" \
        : "=r"(r0),"=r"(r1),"=r"(r2),"=r"(r3) : "r"(addr))

#define LDMT4(r0,r1,r2,r3,addr) \
    asm volatile("ldmatrix.sync.aligned.m8n8.x4.trans.shared.b16 {%0,%1,%2,%3}, [%4];" \
        : "=r"(r0),"=r"(r1),"=r"(r2),"=r"(r3) : "r"(addr))

#define MMAH16816(c, a, b0v, b1v) \
    asm volatile("mma.sync.aligned.m16n8k16.row.col.f32.f16.f16.f32 " \
        "{%0,%1,%2,%3}, {%4,%5,%6,%7}, {%8,%9}, {%0,%1,%2,%3};" \
        : "+f"((c)[0]),"+f"((c)[1]),"+f"((c)[2]),"+f"((c)[3]) \
        : "r"((a)[0]),"r"((a)[1]),"r"((a)[2]),"r"((a)[3]), "r"(b0v),"r"(b1v))

__device__ __forceinline__ uint32_t sw128(uint32_t off) {
    return off ^ ((off >> 3) & 0x70);
}

__device__ __forceinline__ uint32_t pack2h(float x0, float x1) {
    __half2 hp; hp.x = __float2half_rn(x0); hp.y = __float2half_rn(x1);
    return *(uint32_t*)&hp;
}

// ---------------------------------------------------------------------------
// LayerNorm fused -> single fp16
// ---------------------------------------------------------------------------
__global__ __launch_bounds__(256)
void ln_f16_kernel(const float* __restrict__ x, const float* __restrict__ sc,
                   const float* __restrict__ sh, __half* __restrict__ oh)
{
    int row = blockIdx.x;
    int t   = threadIdx.x;
    const float* xr = x + (size_t)row * Cc;
    float4 v = *(const float4*)(xr + t * 4);

    float s  = v.x + v.y + v.z + v.w;
    float s2 = v.x*v.x + v.y*v.y + v.z*v.z + v.w*v.w;
    #pragma unroll
    for (int off = 16; off; off >>= 1) {
        s  += __shfl_down_sync(0xffffffffu, s,  off);
        s2 += __shfl_down_sync(0xffffffffu, s2, off);
    }
    __shared__ float rs[8], rs2[8];
    __shared__ float mean_s, rstd_s;
    int w = t >> 5, lane = t & 31;
    if (lane == 0) { rs[w] = s; rs2[w] = s2; }
    __syncthreads();
    if (t == 0) {
        float ts = 0.f, ts2 = 0.f;
        #pragma unroll
        for (int i = 0; i < 8; i++) { ts += rs[i]; ts2 += rs2[i]; }
        float mean = ts * (1.0f / Cc);
        float var  = ts2 * (1.0f / Cc) - mean * mean;
        mean_s = mean;
        rstd_s = rsqrtf(var + 1e-5f);
    }
    __syncthreads();
    float mean = mean_s, rstd = rstd_s;

    float4 g  = *(const float4*)(sc + t * 4);
    float4 bb = *(const float4*)(sh + t * 4);
    uint2 hp;
    hp.x = pack2h(g.x * (v.x - mean) * rstd + bb.x, g.y * (v.y - mean) * rstd + bb.y);
    hp.y = pack2h(g.z * (v.z - mean) * rstd + bb.z, g.w * (v.w - mean) * rstd + bb.w);
    *(uint2*)(oh + (size_t)row * Cc + t * 4) = hp;
}

// ---------------------------------------------------------------------------
// FUSED weight conversion: all 6 weight transposes + bias concat in ONE kernel.
// ---------------------------------------------------------------------------
__global__ __launch_bounds__(256)
void wconv_all_kernel(const float* __restrict__ Wq, const float* __restrict__ Wk,
                      const float* __restrict__ Wv, const float* __restrict__ Wo,
                      const float* __restrict__ W1, const float* __restrict__ W2,
                      __half* __restrict__ wqkv, __half* __restrict__ wo,
                      __half* __restrict__ w1, __half* __restrict__ w2,
                      const float* __restrict__ bq, const float* __restrict__ bk,
                      const float* __restrict__ bv, float* __restrict__ bqkv)
{
    int bid = blockIdx.x;
    int tid = threadIdx.x;

    if (bid >= 6144) {
        int i = (bid - 6144) * 1024 + tid * 4;
        const float* src = (i < Cc) ? bq : (i < 2*Cc) ? bk : bv;
        float4 v = *(const float4*)(src + (i & (Cc - 1)));
        *(float4*)(bqkv + i) = v;
        return;
    }

    const float* W; __half* Wt; int K, N, t0, nx;
    if (bid < 2048) {
        K = Cc; N = Cc; nx = Cc / 32;
        if      (bid < 512)  { W = Wq; Wt = wqkv;            t0 = 0;    }
        else if (bid < 1024) { W = Wk; Wt = wqkv + Cc*Cc;    t0 = 512;  }
        else if (bid < 1536) { W = Wv; Wt = wqkv + 2*Cc*Cc;  t0 = 1024; }
        else                 { W = Wo; Wt = wo;              t0 = 1536; }
    } else if (bid < 4096) {
        W = W1; Wt = w1; K = Cc; N = Ff; nx = Ff / 32; t0 = 2048;
    } else {
        W = W2; Wt = w2; K = Ff; N = Cc; nx = Cc / 32; t0 = 4096;
    }
    int lt = bid - t0;
    int n0 = (lt % nx) * 32;
    int k0 = (lt / nx) * 64;

    __shared__ float tile[64][33];
    #pragma unroll
    for (int j = 0; j < 8; j++) {
        int idx = tid + j * 256;
        int r = idx >> 5, c = idx & 31;
        tile[r][c] = W[(size_t)(k0 + r) * N + n0 + c];
    }
    __syncthreads();
    int w = tid >> 5, lane = tid & 31;
    #pragma unroll
    for (int j = 0; j < 4; j++) {
        int nl = w + j * 8;
        __half2 hv;
        hv.x = __float2half_rn(tile[2 * lane][nl]);
        hv.y = __float2half_rn(tile[2 * lane + 1][nl]);
        *(__half2*)(Wt + (size_t)(n0 + nl) * K + k0 + 2 * lane) = hv;
    }
}

// ---------------------------------------------------------------------------
// mma.sync single-pass fp16 GEMM.
// Block tile 256x128, BK=64, 8 warps as 4m x 2n (64x64 warp tiles),
// 3-stage cp.async pipeline (48KB/stage, 144KB total), 1 CTA/SM,
// one __syncthreads per k-iter, early prefetch.
// Rationale: 64x64 warp tiles cut LDSM smem traffic per FLOP 1.5x; the old
// 128x128@2CTA config saturated the 128 B/cyc smem crossbar.
// EPI: 1 = bias+GELU -> fp16 [M,N] ; 2 = bias+res -> fp32 [M,N]
//      3 = fused QKV: (acc+bias)*mult -> fp16 [mat,B,H,T,D]
// ---------------------------------------------------------------------------
#define BM 256
#define BN 128
#define STAGE_BYTES (BM*128 + BN*128)   // 49152
#define SMEM_GEMM (3*STAGE_BYTES)       // 147456

template<int EPI>
__global__ __launch_bounds__(256, 1)
void tcgemm(const __half* __restrict__ Aa, const __half* __restrict__ Bw,
            const float* __restrict__ bias, const float* __restrict__ res,
            float* __restrict__ Cf, __half* __restrict__ Coh,
            int K, int N)
{
    extern __shared__ char smem[];
    const uint32_t sb = smem_u32(smem);
    const int tid = threadIdx.x;
    const int m0 = blockIdx.y * BM, n0 = blockIdx.x * BN;
    const int NT = K >> 6;

    const int lane = tid & 31;
    const int wid  = tid >> 5;
    const int wm   = (wid & 3) * 64;
    const int wn   = (wid >> 2) * 64;

    const int a_row = wm + (lane & 15);
    const int a_cb  = (lane >> 4) << 4;
    const int b_row = wn + ((lane >> 4) << 3) + (lane & 7);
    const int b_cb  = ((lane >> 3) & 1) << 4;

    float acc[4][4][8];
    #pragma unroll
    for (int mg = 0; mg < 4; mg++)
        #pragma unroll
        for (int ng = 0; ng < 4; ng++)
            #pragma unroll
            for (int r = 0; r < 8; r++) acc[mg][ng][r] = 0.f;

    auto load_tile = [&](int st, int k0e) {
        uint32_t base = sb + st * STAGE_BYTES;
        // A: 256 rows x 64 cols fp16 = 32KB -> 8 CP16/thread
        #pragma unroll
        for (int j = 0; j < 8; j++) {
            int lin = tid + j * 256;
            int r = lin >> 3, c = lin & 7;
            CP16(base + sw128((uint32_t)(r * 128 + c * 16)),
                 Aa + (size_t)(m0 + r) * K + k0e + c * 8);
        }
        // B: 128 rows x 64 cols = 16KB -> 4 CP16/thread
        #pragma unroll
        for (int j = 0; j < 4; j++) {
            int lin = tid + j * 256;
            int r = lin >> 3, c = lin & 7;
            CP16(base + (uint32_t)(BM * 128) + sw128((uint32_t)(r * 128 + c * 16)),
                 Bw + (size_t)(n0 + r) * K + k0e + c * 8);
        }
        CP_COMMIT();
    };

    load_tile(0, 0);
    if (NT > 1) load_tile(1, 64);

    int stage = 0;
    for (int i = 0; i < NT; i++) {
        if (i + 1 < NT) CP_WAIT1(); else CP_WAIT0();
        __syncthreads();

        // early prefetch: stage (i+2)%3 was consumed at iter i-1, free now
        if (i + 2 < NT) {
            int ns = stage + 2; if (ns >= 3) ns -= 3;
            load_tile(ns, (i + 2) * 64);
        }

        const uint32_t bufA = sb + stage * STAGE_BYTES;
        const uint32_t bufB = bufA + BM * 128;
        #pragma unroll
        for (int ks = 0; ks < 4; ks++) {
            uint32_t a[4][4];
            #pragma unroll
            for (int mg = 0; mg < 4; mg++) {
                uint32_t off = (uint32_t)((a_row + mg * 16) * 128 + ks * 32 + a_cb);
                LDMX4(a[mg][0], a[mg][1], a[mg][2], a[mg][3], bufA + sw128(off));
            }
            #pragma unroll
            for (int ng = 0; ng < 4; ng++) {
                uint32_t b0, b1, b2, b3;
                uint32_t off = (uint32_t)((b_row + ng * 16) * 128 + ks * 32 + b_cb);
                LDMX4(b0, b1, b2, b3, bufB + sw128(off));
                #pragma unroll
                for (int mg = 0; mg < 4; mg++) {
                    MMAH16816(acc[mg][ng] + 0, a[mg], b0, b1);
                    MMAH16816(acc[mg][ng] + 4, a[mg], b2, b3);
                }
            }
        }
        if (++stage == 3) stage = 0;
    }

    const int rbase = m0 + wm + (lane >> 2);
    const int cb0   = n0 + wn + (lane & 3) * 2;
    float bxs[4][2][2];
    #pragma unroll
    for (int ng = 0; ng < 4; ng++)
        #pragma unroll
        for (int ns = 0; ns < 2; ns++) {
            int cc = cb0 + ng * 16 + ns * 8;
            bxs[ng][ns][0] = __ldg(bias + cc);
            bxs[ng][ns][1] = __ldg(bias + cc + 1);
        }

    #pragma unroll
    for (int mg = 0; mg < 4; mg++) {
        #pragma unroll
        for (int ng = 0; ng < 4; ng++) {
            #pragma unroll
            for (int ns = 0; ns < 2; ns++) {
                const float* c4 = acc[mg][ng] + ns * 4;
                int cc = cb0 + ng * 16 + ns * 8;
                float bx = bxs[ng][ns][0], by = bxs[ng][ns][1];
                #pragma unroll
                for (int half = 0; half < 2; half++) {
                    int r = rbase + mg * 16 + half * 8;
                    float vx = c4[half * 2 + 0] + bx;
                    float vy = c4[half * 2 + 1] + by;
                    if (EPI == 1) {
                        vx = 0.5f * vx * (1.0f + erff(vx * 0.70710678118654752f));
                        vy = 0.5f * vy * (1.0f + erff(vy * 0.70710678118654752f));
                        *(uint32_t*)(Coh + (size_t)r * N + cc) = pack2h(vx, vy);
                    } else if (EPI == 3) {
                        int mat = cc >> 10, within = cc & 1023;
                        float mult = (mat == 0) ? 0.125f : 1.0f;   // Q pre-scale
                        int hidx = within >> 6, dd = within & 63;
                        int bidx = r >> 11, t = r & 2047;
                        size_t idx = (size_t)mat * BHTD +
                                     (((size_t)(bidx * Hh + hidx) * Tt + t) * Dd + dd);
                        *(uint32_t*)(Coh + idx) = pack2h(vx * mult, vy * mult);
                    } else {
                        if (EPI == 2) {
                            float2 rr = *(const float2*)(res + (size_t)r * N + cc);
                            vx += rr.x; vy += rr.y;
                        }
                        float2 o; o.x = vx; o.y = vy;
                        *(float2*)(Cf + (size_t)r * N + cc) = o;
                    }
                }
            }
        }
    }
}

// ---------------------------------------------------------------------------
// Causal flash attention, single-pass fp16, 3-stage KV ring with Q recycled
// as stage 2 (48KB, 2 CTAs/SM, one barrier per tile). Unchanged from R15.
// ---------------------------------------------------------------------------
#define SMEM_ATTN (3*16384)

__global__ __launch_bounds__(256, 2)
void attn_mma(const __half* __restrict__ Qq,
              const __half* __restrict__ Kk, const __half* __restrict__ Vv,
              __half* __restrict__ Oh)
{
    extern __shared__ char smem[];
    const uint32_t sb = smem_u32(smem);
    const int tid  = threadIdx.x;
    const int lane = tid & 31;
    const int wid  = tid >> 5;
    const int qt   = (gridDim.x - 1) - blockIdx.x;   // largest tiles first
    const int hd   = blockIdx.y, bz = blockIdx.z;
    const size_t hb = ((size_t)(bz * Hh + hd)) * Tt * Dd;
    const int wm   = wid * 16;

    auto load_kv = [&](int st, int j) {
        #pragma unroll
        for (int jj = 0; jj < 4; jj++) {
            const __half* src = (jj < 2) ? Kk : Vv;
            int within = (jj & 1) * 256 + tid;
            int r = within >> 3, c = within & 7;
            CP16(sb + st * 16384 + (jj >> 1) * 8192 + sw128((uint32_t)(r * 128 + c * 16)),
                 src + hb + (size_t)(j * 64 + r) * Dd + c * 8);
        }
        CP_COMMIT();
    };

    const int ntiles = 2 * qt + 2;

    {
        #pragma unroll
        for (int jj = 0; jj < 4; jj++) {
            int within = jj * 256 + tid;
            int r = within >> 3, c = within & 7;
            CP16(sb + 2 * 16384 + sw128((uint32_t)(r * 128 + c * 16)),
                 Qq + hb + (size_t)(qt * 128 + r) * Dd + c * 8);
        }
        CP_COMMIT();
    }
    load_kv(0, 0);
    load_kv(1, 1);
    CP_WAIT2();
    __syncthreads();

    uint32_t qf[4][4];
    {
        int qrow = wm + (lane & 15);
        int qcb  = (lane >> 4) << 4;
        #pragma unroll
        for (int ks = 0; ks < 4; ks++) {
            uint32_t off = (uint32_t)(qrow * 128 + ks * 32 + qcb);
            LDMX4(qf[ks][0], qf[ks][1], qf[ks][2], qf[ks][3], sb + 2 * 16384 + sw128(off));
        }
    }

    float acc[8][4];
    #pragma unroll
    for (int nt = 0; nt < 8; nt++)
        #pragma unroll
        for (int e = 0; e < 4; e++) acc[nt][e] = 0.f;
    float mrow0 = -1e30f, mrow1 = -1e30f, lrow0 = 0.f, lrow1 = 0.f;

    const int brow = ((lane >> 4) << 3) + (lane & 7);
    const int bcb  = ((lane >> 3) & 1) << 4;
    const int vrow = (((lane >> 3) & 1) << 3) + (lane & 7);
    const int vcb  = (lane >> 4) << 4;

    int stage = 0;
    for (int j = 0; j < ntiles; j++) {
        if (j + 1 < ntiles) CP_WAIT1(); else CP_WAIT0();
        __syncthreads();

        if (j + 2 < ntiles) {
            int ns = stage + 2; if (ns >= 3) ns -= 3;
            load_kv(ns, j + 2);
        }

        const uint32_t st = sb + stage * 16384;

        float s[8][4];
        #pragma unroll
        for (int nt = 0; nt < 8; nt++)
            #pragma unroll
            for (int e = 0; e < 4; e++) s[nt][e] = 0.f;

        #pragma unroll
        for (int ks = 0; ks < 4; ks++) {
            #pragma unroll
            for (int g = 0; g < 4; g++) {
                uint32_t roff = (uint32_t)((g * 16 + brow) * 128 + ks * 32 + bcb);
                uint32_t b0, b1, b2, b3;
                LDMX4(b0, b1, b2, b3, st + sw128(roff));
                MMAH16816(s[2*g],   qf[ks], b0, b1);
                MMAH16816(s[2*g+1], qf[ks], b2, b3);
            }
        }

        if (j >= 2 * qt) {
            int q0 = qt * 128 + wm + (lane >> 2);
            int kb = j * 64 + (lane & 3) * 2;
            #pragma unroll
            for (int nt = 0; nt < 8; nt++) {
                int kg = kb + nt * 8;
                if (kg     > q0)     s[nt][0] = -1e30f;
                if (kg + 1 > q0)     s[nt][1] = -1e30f;
                if (kg     > q0 + 8) s[nt][2] = -1e30f;
                if (kg + 1 > q0 + 8) s[nt][3] = -1e30f;
            }
        }

        float mx0 = -1e30f, mx1 = -1e30f;
        #pragma unroll
        for (int nt = 0; nt < 8; nt++) {
            mx0 = fmaxf(mx0, fmaxf(s[nt][0], s[nt][1]));
            mx1 = fmaxf(mx1, fmaxf(s[nt][2], s[nt][3]));
        }
        mx0 = fmaxf(mx0, __shfl_xor_sync(0xffffffffu, mx0, 1));
        mx0 = fmaxf(mx0, __shfl_xor_sync(0xffffffffu, mx0, 2));
        mx1 = fmaxf(mx1, __shfl_xor_sync(0xffffffffu, mx1, 1));
        mx1 = fmaxf(mx1, __shfl_xor_sync(0xffffffffu, mx1, 2));
        float mn0 = fmaxf(mrow0, mx0), mn1 = fmaxf(mrow1, mx1);
        float fac0 = __expf(mrow0 - mn0), fac1 = __expf(mrow1 - mn1);
        mrow0 = mn0; mrow1 = mn1;

        float lad0 = 0.f, lad1 = 0.f;
        #pragma unroll
        for (int nt = 0; nt < 8; nt++) {
            s[nt][0] = __expf(s[nt][0] - mn0);
            s[nt][1] = __expf(s[nt][1] - mn0);
            s[nt][2] = __expf(s[nt][2] - mn1);
            s[nt][3] = __expf(s[nt][3] - mn1);
            lad0 += s[nt][0] + s[nt][1];
            lad1 += s[nt][2] + s[nt][3];
        }
        lrow0 = lrow0 * fac0 + lad0;
        lrow1 = lrow1 * fac1 + lad1;
        #pragma unroll
        for (int nt = 0; nt < 8; nt++) {
            acc[nt][0] *= fac0; acc[nt][1] *= fac0;
            acc[nt][2] *= fac1; acc[nt][3] *= fac1;
        }

        uint32_t ph[4][4];
        #pragma unroll
        for (int kk = 0; kk < 4; kk++) {
            ph[kk][0] = pack2h(s[2*kk][0],   s[2*kk][1]);
            ph[kk][1] = pack2h(s[2*kk][2],   s[2*kk][3]);
            ph[kk][2] = pack2h(s[2*kk+1][0], s[2*kk+1][1]);
            ph[kk][3] = pack2h(s[2*kk+1][2], s[2*kk+1][3]);
        }

        #pragma unroll
        for (int kk = 0; kk < 4; kk++) {
            #pragma unroll
            for (int g = 0; g < 4; g++) {
                uint32_t roff = (uint32_t)((kk * 16 + vrow) * 128 + g * 32 + vcb);
                uint32_t v0, v1, v2, v3;
                LDMT4(v0, v1, v2, v3, st + 8192 + sw128(roff));
                MMAH16816(acc[2*g],   ph[kk], v0, v1);
                MMAH16816(acc[2*g+1], ph[kk], v2, v3);
            }
        }

        if (++stage == 3) stage = 0;
    }

    lrow0 += __shfl_xor_sync(0xffffffffu, lrow0, 1);
    lrow0 += __shfl_xor_sync(0xffffffffu, lrow0, 2);
    lrow1 += __shfl_xor_sync(0xffffffffu, lrow1, 1);
    lrow1 += __shfl_xor_sync(0xffffffffu, lrow1, 2);
    float inv0 = 1.0f / lrow0, inv1 = 1.0f / lrow1;

    int tok0 = bz * Tt + qt * 128 + wm + (lane >> 2);
    int colb = hd * 64 + (lane & 3) * 2;
    #pragma unroll
    for (int nt = 0; nt < 8; nt++) {
        size_t o0 = (size_t)tok0 * Cc + colb + nt * 8;
        *(uint32_t*)(Oh + o0) = pack2h(acc[nt][0] * inv0, acc[nt][1] * inv0);
        size_t o1 = (size_t)(tok0 + 8) * Cc + colb + nt * 8;
        *(uint32_t*)(Oh + o1) = pack2h(acc[nt][2] * inv1, acc[nt][3] * inv1);
    }
}

// ---------------------------------------------------------------------------
// Launch
// ---------------------------------------------------------------------------
extern "C" void kernel_launch(void* const* d_in, const int* in_sizes, int n_in,
                              void* d_out, int out_size)
{
    const float* x    = (const float*)d_in[0];
    const float* Wq   = (const float*)d_in[1];
    const float* bq   = (const float*)d_in[2];
    const float* Wk   = (const float*)d_in[3];
    const float* bk   = (const float*)d_in[4];
    const float* Wv   = (const float*)d_in[5];
    const float* bv   = (const float*)d_in[6];
    const float* Wo   = (const float*)d_in[7];
    const float* bo   = (const float*)d_in[8];
    const float* W1   = (const float*)d_in[9];
    const float* b1   = (const float*)d_in[10];
    const float* W2   = (const float*)d_in[11];
    const float* b2   = (const float*)d_in[12];
    const float* ln1s = (const float*)d_in[13];
    const float* ln1b = (const float*)d_in[14];
    const float* ln2s = (const float*)d_in[15];
    const float* ln2b = (const float*)d_in[16];
    float* out = (float*)d_out;

    float *x2, *bqkv;
    cudaGetSymbolAddress((void**)&x2,   d_x2);
    cudaGetSymbolAddress((void**)&bqkv, d_bqkv);

    __half *h,*c,*h2,*g;
    __half *wqkv,*wo,*w1,*w2,*qkv;
    cudaGetSymbolAddress((void**)&h,    d_h);
    cudaGetSymbolAddress((void**)&c,    d_c);
    cudaGetSymbolAddress((void**)&h2,   d_h2);
    cudaGetSymbolAddress((void**)&g,    d_g);
    cudaGetSymbolAddress((void**)&qkv,  d_qkv);
    cudaGetSymbolAddress((void**)&wqkv, d_wqkv);
    cudaGetSymbolAddress((void**)&wo,   d_wo);
    cudaGetSymbolAddress((void**)&w1,   d_w1);
    cudaGetSymbolAddress((void**)&w2,   d_w2);

    cudaFuncSetAttribute(tcgemm<1>, cudaFuncAttributeMaxDynamicSharedMemorySize, SMEM_GEMM);
    cudaFuncSetAttribute(tcgemm<2>, cudaFuncAttributeMaxDynamicSharedMemorySize, SMEM_GEMM);
    cudaFuncSetAttribute(tcgemm<3>, cudaFuncAttributeMaxDynamicSharedMemorySize, SMEM_GEMM);
    cudaFuncSetAttribute(attn_mma,  cudaFuncAttributeMaxDynamicSharedMemorySize, SMEM_ATTN);

    // fused weight conversions + bias concat
    wconv_all_kernel<<<6147, 256>>>(Wq, Wk, Wv, Wo, W1, W2,
                                    wqkv, wo, w1, w2, bq, bk, bv, bqkv);

    dim3 grid_qkv(3*Cc/BN, MM/BM);   // (24, 16)
    dim3 grid_o  (Cc/BN,   MM/BM);   // (8, 16)
    dim3 grid_1  (Ff/BN,   MM/BM);   // (32, 16)

    // 1. h = LN1(x) -> fp16
    ln_f16_kernel<<<MM, 256>>>(x, ln1s, ln1b, h);
    // 2. fused QKV -> fp16 [mat,B,H,T,D]; Q pre-scaled by 1/sqrt(D)
    tcgemm<3><<<grid_qkv, 256, SMEM_GEMM>>>(h, wqkv, bqkv, nullptr, nullptr, qkv, Cc, 3*Cc);
    // 3. attention -> ctx fp16
    attn_mma<<<dim3(Tt/128, Hh, Bb), 256, SMEM_ATTN>>>(qkv, qkv + BHTD, qkv + 2*BHTD, c);
    // 4. x2 = x + ctx@Wo + bo
    tcgemm<2><<<grid_o, 256, SMEM_GEMM>>>(c, wo, bo, x, x2, nullptr, Cc, Cc);
    // 5. h2 = LN2(x2) -> fp16
    ln_f16_kernel<<<MM, 256>>>(x2, ln2s, ln2b, h2);
    // 6. g = gelu(h2@W1 + b1) -> fp16
    tcgemm<1><<<grid_1, 256, SMEM_GEMM>>>(h2, w1, b1, nullptr, nullptr, g, Cc, Ff);
    // 7. out = x2 + g@W2 + b2
    tcgemm<2><<<grid_o, 256, SMEM_GEMM>>>(g, w2, b2, x2, out, nullptr, Ff, Cc);
}

// round 17
// speedup vs baseline: 1.0379x; 1.0379x over previous
#include <cuda_runtime.h>
#include <cuda_bf16.h>
#include <cuda_fp16.h>
#include <math.h>
#include <stdint.h>

#define Bb 2
#define Tt 2048
#define Cc 1024
#define Hh 16
#define Dd 64
#define Ff 4096
#define MM (Bb*Tt)
#define BHTD (Bb*Hh*Tt*Dd)

// ---------------------------------------------------------------------------
// Scratch (device globals)
// ---------------------------------------------------------------------------
__device__ float d_x2[MM*Cc];

__device__ __half d_h  [MM*Cc];
__device__ __half d_c  [MM*Cc];     // ctx
__device__ __half d_h2 [MM*Cc];
__device__ __half d_g  [MM*Ff];

// QKV packed: [mat(q/k/v)][B,H,T,D] fp16 (Q pre-scaled by 1/sqrt(D))
__device__ __half d_qkv[3*BHTD];

// transposed weights, [N][K] K-contiguous, single fp16
__device__ __half d_wqkv[3*Cc*Cc];
__device__ __half d_wo[Cc*Cc];
__device__ __half d_w1[Ff*Cc];
__device__ __half d_w2[Cc*Ff];
__device__ float d_bqkv[3*Cc];

// ---------------------------------------------------------------------------
// Helpers
// ---------------------------------------------------------------------------
__device__ __forceinline__ uint32_t smem_u32(const void* p) {
    uint32_t a;
    asm("{ .reg .u64 t; cvta.to.shared.u64 t, %1; cvt.u32.u64 %0, t; }" : "=r"(a) : "l"(p));
    return a;
}

#define CP16(dst, src) asm volatile("cp.async.cg.shared.global [%0], [%1], 16;" :: "r"(dst), "l"(src) : "memory")
#define CP_COMMIT()    asm volatile("cp.async.commit_group;" ::: "memory")
#define CP_WAIT0()     asm volatile("cp.async.wait_group 0;" ::: "memory")
#define CP_WAIT1()     asm volatile("cp.async.wait_group 1;" ::: "memory")
#define CP_WAIT2()     asm volatile("cp.async.wait_group 2;" ::: "memory")

#define LDMX4(r0,r1,r2,r3,addr) \
    asm volatile("ldmatrix.sync.aligned.m8n8.x4.shared.b16 {%0,%1,%2,%3}, [%4];" \
        : "=r"(r0),"=r"(r1),"=r"(r2),"=r"(r3) : "r"(addr))

#define LDMT4(r0,r1,r2,r3,addr) \
    asm volatile("ldmatrix.sync.aligned.m8n8.x4.trans.shared.b16 {%0,%1,%2,%3}, [%4];" \
        : "=r"(r0),"=r"(r1),"=r"(r2),"=r"(r3) : "r"(addr))

#define MMAH16816(c, a, b0v, b1v) \
    asm volatile("mma.sync.aligned.m16n8k16.row.col.f32.f16.f16.f32 " \
        "{%0,%1,%2,%3}, {%4,%5,%6,%7}, {%8,%9}, {%0,%1,%2,%3};" \
        : "+f"((c)[0]),"+f"((c)[1]),"+f"((c)[2]),"+f"((c)[3]) \
        : "r"((a)[0]),"r"((a)[1]),"r"((a)[2]),"r"((a)[3]), "r"(b0v),"r"(b1v))

__device__ __forceinline__ uint32_t sw128(uint32_t off) {
    return off ^ ((off >> 3) & 0x70);
}

__device__ __forceinline__ uint32_t pack2h(float x0, float x1) {
    __half2 hp; hp.x = __float2half_rn(x0); hp.y = __float2half_rn(x1);
    return *(uint32_t*)&hp;
}

// ---------------------------------------------------------------------------
// LayerNorm, warp-per-row -> single fp16. 8 rows/block, no barriers, no smem.
// Lane owns cols {lane*4 + k*128 : k=0..7} (coalesced float4 loads/stores).
// ---------------------------------------------------------------------------
__global__ __launch_bounds__(256)
void ln_f16_kernel(const float* __restrict__ x, const float* __restrict__ sc,
                   const float* __restrict__ sh, __half* __restrict__ oh)
{
    int warp = threadIdx.x >> 5;
    int lane = threadIdx.x & 31;
    int row  = blockIdx.x * 8 + warp;

    const float* xr = x + (size_t)row * Cc;
    float4 v[8];
    float s = 0.f, s2 = 0.f;
    #pragma unroll
    for (int k = 0; k < 8; k++) {
        v[k] = *(const float4*)(xr + lane * 4 + k * 128);
        s  += v[k].x + v[k].y + v[k].z + v[k].w;
        s2 += v[k].x*v[k].x + v[k].y*v[k].y + v[k].z*v[k].z + v[k].w*v[k].w;
    }
    #pragma unroll
    for (int off = 16; off; off >>= 1) {
        s  += __shfl_xor_sync(0xffffffffu, s,  off);
        s2 += __shfl_xor_sync(0xffffffffu, s2, off);
    }
    float mean = s * (1.0f / Cc);
    float var  = s2 * (1.0f / Cc) - mean * mean;
    float rstd = rsqrtf(var + 1e-5f);

    #pragma unroll
    for (int k = 0; k < 8; k++) {
        int col = lane * 4 + k * 128;
        float4 g  = *(const float4*)(sc + col);
        float4 bb = *(const float4*)(sh + col);
        uint2 hp;
        hp.x = pack2h(g.x * (v[k].x - mean) * rstd + bb.x,
                      g.y * (v[k].y - mean) * rstd + bb.y);
        hp.y = pack2h(g.z * (v[k].z - mean) * rstd + bb.z,
                      g.w * (v[k].w - mean) * rstd + bb.w);
        *(uint2*)(oh + (size_t)row * Cc + col) = hp;
    }
}

// ---------------------------------------------------------------------------
// FUSED weight conversion: all 6 weight transposes + bias concat in ONE kernel.
// ---------------------------------------------------------------------------
__global__ __launch_bounds__(256)
void wconv_all_kernel(const float* __restrict__ Wq, const float* __restrict__ Wk,
                      const float* __restrict__ Wv, const float* __restrict__ Wo,
                      const float* __restrict__ W1, const float* __restrict__ W2,
                      __half* __restrict__ wqkv, __half* __restrict__ wo,
                      __half* __restrict__ w1, __half* __restrict__ w2,
                      const float* __restrict__ bq, const float* __restrict__ bk,
                      const float* __restrict__ bv, float* __restrict__ bqkv)
{
    int bid = blockIdx.x;
    int tid = threadIdx.x;

    if (bid >= 6144) {
        int i = (bid - 6144) * 1024 + tid * 4;
        const float* src = (i < Cc) ? bq : (i < 2*Cc) ? bk : bv;
        float4 v = *(const float4*)(src + (i & (Cc - 1)));
        *(float4*)(bqkv + i) = v;
        return;
    }

    const float* W; __half* Wt; int K, N, t0, nx;
    if (bid < 2048) {
        K = Cc; N = Cc; nx = Cc / 32;
        if      (bid < 512)  { W = Wq; Wt = wqkv;            t0 = 0;    }
        else if (bid < 1024) { W = Wk; Wt = wqkv + Cc*Cc;    t0 = 512;  }
        else if (bid < 1536) { W = Wv; Wt = wqkv + 2*Cc*Cc;  t0 = 1024; }
        else                 { W = Wo; Wt = wo;              t0 = 1536; }
    } else if (bid < 4096) {
        W = W1; Wt = w1; K = Cc; N = Ff; nx = Ff / 32; t0 = 2048;
    } else {
        W = W2; Wt = w2; K = Ff; N = Cc; nx = Cc / 32; t0 = 4096;
    }
    int lt = bid - t0;
    int n0 = (lt % nx) * 32;
    int k0 = (lt / nx) * 64;

    __shared__ float tile[64][33];
    #pragma unroll
    for (int j = 0; j < 8; j++) {
        int idx = tid + j * 256;
        int r = idx >> 5, c = idx & 31;
        tile[r][c] = W[(size_t)(k0 + r) * N + n0 + c];
    }
    __syncthreads();
    int w = tid >> 5, lane = tid & 31;
    #pragma unroll
    for (int j = 0; j < 4; j++) {
        int nl = w + j * 8;
        __half2 hv;
        hv.x = __float2half_rn(tile[2 * lane][nl]);
        hv.y = __float2half_rn(tile[2 * lane + 1][nl]);
        *(__half2*)(Wt + (size_t)(n0 + nl) * K + k0 + 2 * lane) = hv;
    }
}

// ---------------------------------------------------------------------------
// mma.sync single-pass fp16 GEMM (proven R15 config):
// Block tile 128x128, BK=64, 3-stage cp.async pipeline, early prefetch,
// 2 CTAs/SM, one __syncthreads per k-iter.
// EPI: 1 = bias+GELU -> fp16 [M,N] ; 2 = bias+res -> fp32 [M,N]
//      3 = fused QKV: (acc+bias)*mult -> fp16 [mat,B,H,T,D]
// ---------------------------------------------------------------------------
#define SMEM_GEMM (3*32768)

template<int EPI>
__global__ __launch_bounds__(256, 2)
void tcgemm(const __half* __restrict__ Aa, const __half* __restrict__ Bw,
            const float* __restrict__ bias, const float* __restrict__ res,
            float* __restrict__ Cf, __half* __restrict__ Coh,
            int K, int N)
{
    extern __shared__ char smem[];
    const uint32_t sb = smem_u32(smem);
    const int tid = threadIdx.x;
    const int m0 = blockIdx.y * 128, n0 = blockIdx.x * 128;
    const int NT = K >> 6;

    const int lane = tid & 31;
    const int wid  = tid >> 5;
    const int wm   = (wid & 3) * 32;
    const int wn   = (wid >> 2) * 64;

    const int a_row = wm + (lane & 15);
    const int a_cb  = (lane >> 4) << 4;
    const int b_row = wn + ((lane >> 4) << 3) + (lane & 7);
    const int b_cb  = ((lane >> 3) & 1) << 4;

    float acc[2][4][8];
    #pragma unroll
    for (int mg = 0; mg < 2; mg++)
        #pragma unroll
        for (int ng = 0; ng < 4; ng++)
            #pragma unroll
            for (int r = 0; r < 8; r++) acc[mg][ng][r] = 0.f;

    auto load_tile = [&](int st, int k0e) {
        uint32_t base = sb + st * 32768;
        #pragma unroll
        for (int j = 0; j < 4; j++) {
            int lin = tid + j * 256;
            int r = lin >> 3, c = lin & 7;
            uint32_t sw = sw128((uint32_t)(r * 128 + c * 16));
            CP16(base + sw,         Aa + (size_t)(m0 + r) * K + k0e + c * 8);
            CP16(base + 16384 + sw, Bw + (size_t)(n0 + r) * K + k0e + c * 8);
        }
        CP_COMMIT();
    };

    load_tile(0, 0);
    if (NT > 1) load_tile(1, 64);

    int stage = 0;
    for (int i = 0; i < NT; i++) {
        if (i + 1 < NT) CP_WAIT1(); else CP_WAIT0();
        __syncthreads();

        // early prefetch: stage (i+2)%3 was consumed at iter i-1, free now
        if (i + 2 < NT) {
            int ns = stage + 2; if (ns >= 3) ns -= 3;
            load_tile(ns, (i + 2) * 64);
        }

        const uint32_t bufA = sb + stage * 32768;
        const uint32_t bufB = bufA + 16384;
        #pragma unroll
        for (int ks = 0; ks < 4; ks++) {
            uint32_t a[2][4];
            #pragma unroll
            for (int mg = 0; mg < 2; mg++) {
                uint32_t off = (uint32_t)((a_row + mg * 16) * 128 + ks * 32 + a_cb);
                LDMX4(a[mg][0], a[mg][1], a[mg][2], a[mg][3], bufA + sw128(off));
            }
            #pragma unroll
            for (int ng = 0; ng < 4; ng++) {
                uint32_t b0, b1, b2, b3;
                uint32_t off = (uint32_t)((b_row + ng * 16) * 128 + ks * 32 + b_cb);
                LDMX4(b0, b1, b2, b3, bufB + sw128(off));
                #pragma unroll
                for (int mg = 0; mg < 2; mg++) {
                    MMAH16816(acc[mg][ng] + 0, a[mg], b0, b1);
                    MMAH16816(acc[mg][ng] + 4, a[mg], b2, b3);
                }
            }
        }
        if (++stage == 3) stage = 0;
    }

    const int rbase = m0 + wm + (lane >> 2);
    const int cb0   = n0 + wn + (lane & 3) * 2;
    float bxs[4][2][2];
    #pragma unroll
    for (int ng = 0; ng < 4; ng++)
        #pragma unroll
        for (int ns = 0; ns < 2; ns++) {
            int cc = cb0 + ng * 16 + ns * 8;
            bxs[ng][ns][0] = __ldg(bias + cc);
            bxs[ng][ns][1] = __ldg(bias + cc + 1);
        }

    #pragma unroll
    for (int mg = 0; mg < 2; mg++) {
        #pragma unroll
        for (int ng = 0; ng < 4; ng++) {
            #pragma unroll
            for (int ns = 0; ns < 2; ns++) {
                const float* c4 = acc[mg][ng] + ns * 4;
                int cc = cb0 + ng * 16 + ns * 8;
                float bx = bxs[ng][ns][0], by = bxs[ng][ns][1];
                #pragma unroll
                for (int half = 0; half < 2; half++) {
                    int r = rbase + mg * 16 + half * 8;
                    float vx = c4[half * 2 + 0] + bx;
                    float vy = c4[half * 2 + 1] + by;
                    if (EPI == 1) {
                        vx = 0.5f * vx * (1.0f + erff(vx * 0.70710678118654752f));
                        vy = 0.5f * vy * (1.0f + erff(vy * 0.70710678118654752f));
                        *(uint32_t*)(Coh + (size_t)r * N + cc) = pack2h(vx, vy);
                    } else if (EPI == 3) {
                        int mat = cc >> 10, within = cc & 1023;
                        float mult = (mat == 0) ? 0.125f : 1.0f;   // Q pre-scale
                        int hidx = within >> 6, dd = within & 63;
                        int bidx = r >> 11, t = r & 2047;
                        size_t idx = (size_t)mat * BHTD +
                                     (((size_t)(bidx * Hh + hidx) * Tt + t) * Dd + dd);
                        *(uint32_t*)(Coh + idx) = pack2h(vx * mult, vy * mult);
                    } else {
                        if (EPI == 2) {
                            float2 rr = *(const float2*)(res + (size_t)r * N + cc);
                            vx += rr.x; vy += rr.y;
                        }
                        float2 o; o.x = vx; o.y = vy;
                        *(float2*)(Cf + (size_t)r * N + cc) = o;
                    }
                }
            }
        }
    }
}

// ---------------------------------------------------------------------------
// Causal flash attention, single-pass fp16, 3-stage KV ring with Q recycled
// as stage 2 (48KB, 2 CTAs/SM, one barrier per tile). Unchanged from R15.
// ---------------------------------------------------------------------------
#define SMEM_ATTN (3*16384)

__global__ __launch_bounds__(256, 2)
void attn_mma(const __half* __restrict__ Qq,
              const __half* __restrict__ Kk, const __half* __restrict__ Vv,
              __half* __restrict__ Oh)
{
    extern __shared__ char smem[];
    const uint32_t sb = smem_u32(smem);
    const int tid  = threadIdx.x;
    const int lane = tid & 31;
    const int wid  = tid >> 5;
    const int qt   = (gridDim.x - 1) - blockIdx.x;   // largest tiles first
    const int hd   = blockIdx.y, bz = blockIdx.z;
    const size_t hb = ((size_t)(bz * Hh + hd)) * Tt * Dd;
    const int wm   = wid * 16;

    auto load_kv = [&](int st, int j) {
        #pragma unroll
        for (int jj = 0; jj < 4; jj++) {
            const __half* src = (jj < 2) ? Kk : Vv;
            int within = (jj & 1) * 256 + tid;
            int r = within >> 3, c = within & 7;
            CP16(sb + st * 16384 + (jj >> 1) * 8192 + sw128((uint32_t)(r * 128 + c * 16)),
                 src + hb + (size_t)(j * 64 + r) * Dd + c * 8);
        }
        CP_COMMIT();
    };

    const int ntiles = 2 * qt + 2;

    {
        #pragma unroll
        for (int jj = 0; jj < 4; jj++) {
            int within = jj * 256 + tid;
            int r = within >> 3, c = within & 7;
            CP16(sb + 2 * 16384 + sw128((uint32_t)(r * 128 + c * 16)),
                 Qq + hb + (size_t)(qt * 128 + r) * Dd + c * 8);
        }
        CP_COMMIT();
    }
    load_kv(0, 0);
    load_kv(1, 1);
    CP_WAIT2();
    __syncthreads();

    uint32_t qf[4][4];
    {
        int qrow = wm + (lane & 15);
        int qcb  = (lane >> 4) << 4;
        #pragma unroll
        for (int ks = 0; ks < 4; ks++) {
            uint32_t off = (uint32_t)(qrow * 128 + ks * 32 + qcb);
            LDMX4(qf[ks][0], qf[ks][1], qf[ks][2], qf[ks][3], sb + 2 * 16384 + sw128(off));
        }
    }

    float acc[8][4];
    #pragma unroll
    for (int nt = 0; nt < 8; nt++)
        #pragma unroll
        for (int e = 0; e < 4; e++) acc[nt][e] = 0.f;
    float mrow0 = -1e30f, mrow1 = -1e30f, lrow0 = 0.f, lrow1 = 0.f;

    const int brow = ((lane >> 4) << 3) + (lane & 7);
    const int bcb  = ((lane >> 3) & 1) << 4;
    const int vrow = (((lane >> 3) & 1) << 3) + (lane & 7);
    const int vcb  = (lane >> 4) << 4;

    int stage = 0;
    for (int j = 0; j < ntiles; j++) {
        if (j + 1 < ntiles) CP_WAIT1(); else CP_WAIT0();
        __syncthreads();

        if (j + 2 < ntiles) {
            int ns = stage + 2; if (ns >= 3) ns -= 3;
            load_kv(ns, j + 2);
        }

        const uint32_t st = sb + stage * 16384;

        float s[8][4];
        #pragma unroll
        for (int nt = 0; nt < 8; nt++)
            #pragma unroll
            for (int e = 0; e < 4; e++) s[nt][e] = 0.f;

        #pragma unroll
        for (int ks = 0; ks < 4; ks++) {
            #pragma unroll
            for (int g = 0; g < 4; g++) {
                uint32_t roff = (uint32_t)((g * 16 + brow) * 128 + ks * 32 + bcb);
                uint32_t b0, b1, b2, b3;
                LDMX4(b0, b1, b2, b3, st + sw128(roff));
                MMAH16816(s[2*g],   qf[ks], b0, b1);
                MMAH16816(s[2*g+1], qf[ks], b2, b3);
            }
        }

        if (j >= 2 * qt) {
            int q0 = qt * 128 + wm + (lane >> 2);
            int kb = j * 64 + (lane & 3) * 2;
            #pragma unroll
            for (int nt = 0; nt < 8; nt++) {
                int kg = kb + nt * 8;
                if (kg     > q0)     s[nt][0] = -1e30f;
                if (kg + 1 > q0)     s[nt][1] = -1e30f;
                if (kg     > q0 + 8) s[nt][2] = -1e30f;
                if (kg + 1 > q0 + 8) s[nt][3] = -1e30f;
            }
        }

        float mx0 = -1e30f, mx1 = -1e30f;
        #pragma unroll
        for (int nt = 0; nt < 8; nt++) {
            mx0 = fmaxf(mx0, fmaxf(s[nt][0], s[nt][1]));
            mx1 = fmaxf(mx1, fmaxf(s[nt][2], s[nt][3]));
        }
        mx0 = fmaxf(mx0, __shfl_xor_sync(0xffffffffu, mx0, 1));
        mx0 = fmaxf(mx0, __shfl_xor_sync(0xffffffffu, mx0, 2));
        mx1 = fmaxf(mx1, __shfl_xor_sync(0xffffffffu, mx1, 1));
        mx1 = fmaxf(mx1, __shfl_xor_sync(0xffffffffu, mx1, 2));
        float mn0 = fmaxf(mrow0, mx0), mn1 = fmaxf(mrow1, mx1);
        float fac0 = __expf(mrow0 - mn0), fac1 = __expf(mrow1 - mn1);
        mrow0 = mn0; mrow1 = mn1;

        float lad0 = 0.f, lad1 = 0.f;
        #pragma unroll
        for (int nt = 0; nt < 8; nt++) {
            s[nt][0] = __expf(s[nt][0] - mn0);
            s[nt][1] = __expf(s[nt][1] - mn0);
            s[nt][2] = __expf(s[nt][2] - mn1);
            s[nt][3] = __expf(s[nt][3] - mn1);
            lad0 += s[nt][0] + s[nt][1];
            lad1 += s[nt][2] + s[nt][3];
        }
        lrow0 = lrow0 * fac0 + lad0;
        lrow1 = lrow1 * fac1 + lad1;
        #pragma unroll
        for (int nt = 0; nt < 8; nt++) {
            acc[nt][0] *= fac0; acc[nt][1] *= fac0;
            acc[nt][2] *= fac1; acc[nt][3] *= fac1;
        }

        uint32_t ph[4][4];
        #pragma unroll
        for (int kk = 0; kk < 4; kk++) {
            ph[kk][0] = pack2h(s[2*kk][0],   s[2*kk][1]);
            ph[kk][1] = pack2h(s[2*kk][2],   s[2*kk][3]);
            ph[kk][2] = pack2h(s[2*kk+1][0], s[2*kk+1][1]);
            ph[kk][3] = pack2h(s[2*kk+1][2], s[2*kk+1][3]);
        }

        #pragma unroll
        for (int kk = 0; kk < 4; kk++) {
            #pragma unroll
            for (int g = 0; g < 4; g++) {
                uint32_t roff = (uint32_t)((kk * 16 + vrow) * 128 + g * 32 + vcb);
                uint32_t v0, v1, v2, v3;
                LDMT4(v0, v1, v2, v3, st + 8192 + sw128(roff));
                MMAH16816(acc[2*g],   ph[kk], v0, v1);
                MMAH16816(acc[2*g+1], ph[kk], v2, v3);
            }
        }

        if (++stage == 3) stage = 0;
    }

    lrow0 += __shfl_xor_sync(0xffffffffu, lrow0, 1);
    lrow0 += __shfl_xor_sync(0xffffffffu, lrow0, 2);
    lrow1 += __shfl_xor_sync(0xffffffffu, lrow1, 1);
    lrow1 += __shfl_xor_sync(0xffffffffu, lrow1, 2);
    float inv0 = 1.0f / lrow0, inv1 = 1.0f / lrow1;

    int tok0 = bz * Tt + qt * 128 + wm + (lane >> 2);
    int colb = hd * 64 + (lane & 3) * 2;
    #pragma unroll
    for (int nt = 0; nt < 8; nt++) {
        size_t o0 = (size_t)tok0 * Cc + colb + nt * 8;
        *(uint32_t*)(Oh + o0) = pack2h(acc[nt][0] * inv0, acc[nt][1] * inv0);
        size_t o1 = (size_t)(tok0 + 8) * Cc + colb + nt * 8;
        *(uint32_t*)(Oh + o1) = pack2h(acc[nt][2] * inv1, acc[nt][3] * inv1);
    }
}

// ---------------------------------------------------------------------------
// Launch
// ---------------------------------------------------------------------------
extern "C" void kernel_launch(void* const* d_in, const int* in_sizes, int n_in,
                              void* d_out, int out_size)
{
    const float* x    = (const float*)d_in[0];
    const float* Wq   = (const float*)d_in[1];
    const float* bq   = (const float*)d_in[2];
    const float* Wk   = (const float*)d_in[3];
    const float* bk   = (const float*)d_in[4];
    const float* Wv   = (const float*)d_in[5];
    const float* bv   = (const float*)d_in[6];
    const float* Wo   = (const float*)d_in[7];
    const float* bo   = (const float*)d_in[8];
    const float* W1   = (const float*)d_in[9];
    const float* b1   = (const float*)d_in[10];
    const float* W2   = (const float*)d_in[11];
    const float* b2   = (const float*)d_in[12];
    const float* ln1s = (const float*)d_in[13];
    const float* ln1b = (const float*)d_in[14];
    const float* ln2s = (const float*)d_in[15];
    const float* ln2b = (const float*)d_in[16];
    float* out = (float*)d_out;

    float *x2, *bqkv;
    cudaGetSymbolAddress((void**)&x2,   d_x2);
    cudaGetSymbolAddress((void**)&bqkv, d_bqkv);

    __half *h,*c,*h2,*g;
    __half *wqkv,*wo,*w1,*w2,*qkv;
    cudaGetSymbolAddress((void**)&h,    d_h);
    cudaGetSymbolAddress((void**)&c,    d_c);
    cudaGetSymbolAddress((void**)&h2,   d_h2);
    cudaGetSymbolAddress((void**)&g,    d_g);
    cudaGetSymbolAddress((void**)&qkv,  d_qkv);
    cudaGetSymbolAddress((void**)&wqkv, d_wqkv);
    cudaGetSymbolAddress((void**)&wo,   d_wo);
    cudaGetSymbolAddress((void**)&w1,   d_w1);
    cudaGetSymbolAddress((void**)&w2,   d_w2);

    cudaFuncSetAttribute(tcgemm<1>, cudaFuncAttributeMaxDynamicSharedMemorySize, SMEM_GEMM);
    cudaFuncSetAttribute(tcgemm<2>, cudaFuncAttributeMaxDynamicSharedMemorySize, SMEM_GEMM);
    cudaFuncSetAttribute(tcgemm<3>, cudaFuncAttributeMaxDynamicSharedMemorySize, SMEM_GEMM);
    cudaFuncSetAttribute(attn_mma,  cudaFuncAttributeMaxDynamicSharedMemorySize, SMEM_ATTN);

    // fused weight conversions + bias concat
    wconv_all_kernel<<<6147, 256>>>(Wq, Wk, Wv, Wo, W1, W2,
                                    wqkv, wo, w1, w2, bq, bk, bv, bqkv);

    dim3 grid_qkv(3*Cc/128, MM/128);   // (24, 32)
    dim3 grid_o  (Cc/128,   MM/128);   // (8, 32)
    dim3 grid_1  (Ff/128,   MM/128);   // (32, 32)

    // 1. h = LN1(x) -> fp16 (warp-per-row)
    ln_f16_kernel<<<MM/8, 256>>>(x, ln1s, ln1b, h);
    // 2. fused QKV -> fp16 [mat,B,H,T,D]; Q pre-scaled by 1/sqrt(D)
    tcgemm<3><<<grid_qkv, 256, SMEM_GEMM>>>(h, wqkv, bqkv, nullptr, nullptr, qkv, Cc, 3*Cc);
    // 3. attention -> ctx fp16
    attn_mma<<<dim3(Tt/128, Hh, Bb), 256, SMEM_ATTN>>>(qkv, qkv + BHTD, qkv + 2*BHTD, c);
    // 4. x2 = x + ctx@Wo + bo
    tcgemm<2><<<grid_o, 256, SMEM_GEMM>>>(c, wo, bo, x, x2, nullptr, Cc, Cc);
    // 5. h2 = LN2(x2) -> fp16 (warp-per-row)
    ln_f16_kernel<<<MM/8, 256>>>(x2, ln2s, ln2b, h2);
    // 6. g = gelu(h2@W1 + b1) -> fp16
    tcgemm<1><<<grid_1, 256, SMEM_GEMM>>>(h2, w1, b1, nullptr, nullptr, g, Cc, Ff);
    // 7. out = x2 + g@W2 + b2
    tcgemm<2><<<grid_o, 256, SMEM_GEMM>>>(g, w2, b2, x2, out, nullptr, Ff, Cc);
}